// round 14
// baseline (speedup 1.0000x reference)
#include <cuda_runtime.h>
#include <cuda_bf16.h>

// DigitCaps fused single-kernel for GB300 (sm_103a), round 12: occupancy-3.
// (Third submission — two prior attempts died to broker infra, no signal.)
//   output[b,c] = (sum_n u[b,n,:]) . dc_new[c,:] / N
//   dc_new      = dc + (seg_u - counts*dc) / (B*N)
// Deltas vs r11: dc in bf16x2 regs (20 vs 80) + bf16 sims; JB 32->16 so smem
// 72.5KB -> 3 blocks/SM (24 warps); FMNMX-tree mantissa-key argmax; ull2 W reads.

#define Bsz    128
#define Jtot   4608
#define Cc     10
#define Dd     8
#define Mm     4
#define Ntot   (Jtot * Mm)          // 18432

#define JB     16
#define BB     32
#define NTHR   256
#define WSTR   260                  // padded W row stride (floats), rows 16B-aligned
#define XSTR   130                  // padded X row stride (floats)
#define NSEG   40                   // bf16x2 seg slots (counts in registers)
#define NBLK   ((Jtot / JB) * (Bsz / BB))   // 288 * 4 = 1152

// scratch: [0,1024) sum_u[b][d]; [1024,1104) seg[c*8+d]; [1104,1114) cnt[c]
__device__ float    g_scratch[1120];
__device__ unsigned g_done;

// ---- packed f32x2 helpers ----
__device__ __forceinline__ unsigned long long pk2(float lo, float hi) {
    unsigned long long r;
    asm("mov.b64 %0, {%1, %2};" : "=l"(r) : "f"(lo), "f"(hi));
    return r;
}
__device__ __forceinline__ float2 upk2(unsigned long long a) {
    float2 r;
    asm("mov.b64 {%0, %1}, %2;" : "=f"(r.x), "=f"(r.y) : "l"(a));
    return r;
}
__device__ __forceinline__ unsigned long long fma2(unsigned long long a,
                                                   unsigned long long b,
                                                   unsigned long long c) {
    unsigned long long d;
    asm("fma.rn.f32x2 %0, %1, %2, %3;" : "=l"(d) : "l"(a), "l"(b), "l"(c));
    return d;
}
__device__ __forceinline__ unsigned long long add2(unsigned long long a,
                                                   unsigned long long b) {
    unsigned long long d;
    asm("add.rn.f32x2 %0, %1, %2;" : "=l"(d) : "l"(a), "l"(b));
    return d;
}
// (lo,hi) f32 pair -> bf16x2 (lo in bits[15:0])
__device__ __forceinline__ unsigned cvt_bf16x2(unsigned long long p) {
    float2 t = upk2(p);
    unsigned r;
    asm("cvt.rn.bf16x2.f32 %0, %1, %2;" : "=r"(r) : "f"(t.y), "f"(t.x));
    return r;
}
__device__ __forceinline__ __nv_bfloat162 as_bf2(unsigned v) {
    return *(__nv_bfloat162*)&v;
}

extern __shared__ float smem[];

__global__ __launch_bounds__(NTHR, 3)
void caps_main_kernel(const float* __restrict__ xin,   // [B, J, 8]
                      const float* __restrict__ Wg,    // [J, 8, 32]
                      const float* __restrict__ dcg,   // [10, 8]
                      float* __restrict__ out)         // [128*10 + 80]
{
    float*    sW   = smem;                               // JB*WSTR = 4160 f
    float*    sX   = sW + JB * WSTR;                     // BB*XSTR = 4160 f
    unsigned* sSeg = (unsigned*)(sX + BB * XSTR);        // NSEG*256 u32

    const int tid = threadIdx.x;
    const int j0  = blockIdx.x * JB;
    const int b0  = blockIdx.y * BB;

    // ---- stage W tile: 16 rows x 64 float4 ----
    {
        const float4* src = (const float4*)(Wg + (size_t)j0 * 256);
        #pragma unroll
        for (int i = tid; i < JB * 64; i += NTHR) {
            int jl = i >> 6, r = i & 63;
            ((float4*)(sW + jl * WSTR))[r] = src[i];
        }
    }
    // ---- stage X tile: 32 rows x 64 float2 ----
    {
        #pragma unroll
        for (int i = tid; i < BB * 64; i += NTHR) {
            int bl = i >> 6, r = i & 63;
            const float2* src =
                (const float2*)(xin + (size_t)(b0 + bl) * (Jtot * 8) + (size_t)j0 * 8);
            ((float2*)(sX + bl * XSTR))[r] = src[r];
        }
    }
    // ---- zero private seg columns ----
    for (int i = tid; i < NSEG * 256; i += NTHR) sSeg[i] = 0u;

    // ---- digit_caps as 40 bf16x2 (d-pair) registers ----
    __nv_bfloat162 rdc[Cc * 4];
    #pragma unroll
    for (int i = 0; i < Cc * 4; i++) {
        float2 v = ((const float2*)dcg)[i];
        rdc[i] = __float22bfloat162_rn(v);
    }

    __syncthreads();

    const int bl  = tid >> 3;
    const int sub = tid & 7;
    const int b   = b0 + bl;

    unsigned long long su0 = 0, su1 = 0, su2 = 0, su3 = 0;
    unsigned long long cnt = 0;     // 10 x 6-bit packed counts (max 8/thread)
    const float* xrow = sX + bl * XSTR;

    for (int it = 0; it < 8; ++it) {
        const int p  = it * 8 + sub;   // 0..63
        const int jl = p >> 2;
        const int m  = p & 3;

        const float2*     xs   = (const float2*)(xrow + jl * 8);
        const ulonglong2* wrow = (const ulonglong2*)(sW + jl * WSTR);

        unsigned long long u0 = 0, u1 = 0, u2 = 0, u3 = 0;
        #pragma unroll
        for (int k = 0; k < 4; k++) {
            float2 xp = xs[k];
            unsigned long long xa = pk2(xp.x, xp.x);
            unsigned long long xb = pk2(xp.y, xp.y);
            ulonglong2 wA = wrow[(2 * k) * 8 + m * 2];
            ulonglong2 wB = wrow[(2 * k) * 8 + m * 2 + 1];
            u0 = fma2(xa, wA.x, u0);
            u1 = fma2(xa, wA.y, u1);
            u2 = fma2(xa, wB.x, u2);
            u3 = fma2(xa, wB.y, u3);
            ulonglong2 wC = wrow[(2 * k + 1) * 8 + m * 2];
            ulonglong2 wD = wrow[(2 * k + 1) * 8 + m * 2 + 1];
            u0 = fma2(xb, wC.x, u0);
            u1 = fma2(xb, wC.y, u1);
            u2 = fma2(xb, wD.x, u2);
            u3 = fma2(xb, wD.y, u3);
        }

        su0 = add2(su0, u0); su1 = add2(su1, u1);
        su2 = add2(su2, u2); su3 = add2(su3, u3);

        // bf16 votes (used by sims AND seg accumulation)
        unsigned v0 = cvt_bf16x2(u0), v1 = cvt_bf16x2(u1);
        unsigned v2 = cvt_bf16x2(u2), v3 = cvt_bf16x2(u3);
        __nv_bfloat162 V0 = as_bf2(v0), V1 = as_bf2(v1);
        __nv_bfloat162 V2 = as_bf2(v2), V3 = as_bf2(v3);

        // sims: bf16x2 dots; pack (15-c) into low 4 mantissa bits; FMNMX tree.
        // Sub-ulp tie-break deviation only (inverted for negative near-ties).
        float key[Cc];
        #pragma unroll
        for (int c = 0; c < Cc; c++) {
            __nv_bfloat162 t0 = __hfma2(V1, rdc[c * 4 + 1], __hmul2(V0, rdc[c * 4]));
            __nv_bfloat162 t1 = __hfma2(V3, rdc[c * 4 + 3], __hmul2(V2, rdc[c * 4 + 2]));
            __nv_bfloat162 a  = __hadd2(t0, t1);
            unsigned ab = *(unsigned*)&a;
            float s = __uint_as_float(ab << 16) + __uint_as_float(ab & 0xFFFF0000u);
            key[c] = __uint_as_float((__float_as_uint(s) & 0xFFFFFFF0u)
                                     | (unsigned)(15 - c));      // one LOP3
        }
        float m01 = fmaxf(key[0], key[1]);
        float m23 = fmaxf(key[2], key[3]);
        float m45 = fmaxf(key[4], key[5]);
        float m67 = fmaxf(key[6], key[7]);
        float m89 = fmaxf(key[8], key[9]);
        float ma  = fmaxf(m01, m23);
        float mb  = fmaxf(m45, m67);
        float best = fmaxf(fmaxf(ma, mb), m89);
        const int wbest = 15 - (int)(__float_as_uint(best) & 0xFu);

        // per-thread-private bf16x2 seg columns (bank = tid%32, conflict-free)
        unsigned* segp = sSeg + wbest * 4 * 256 + tid;
        {
            unsigned o;
            __nv_bfloat162 r;
            o = segp[0];   r = __hadd2(as_bf2(o), V0); segp[0]   = *(unsigned*)&r;
            o = segp[256]; r = __hadd2(as_bf2(o), V1); segp[256] = *(unsigned*)&r;
            o = segp[512]; r = __hadd2(as_bf2(o), V2); segp[512] = *(unsigned*)&r;
            o = segp[768]; r = __hadd2(as_bf2(o), V3); segp[768] = *(unsigned*)&r;
        }
        cnt += 1ull << (6 * wbest);
    }

    // ---- sum_u: reduce over the 8 threads sharing b ----
    #pragma unroll
    for (int d = 1; d < 8; d <<= 1) {
        su0 = add2(su0, __shfl_xor_sync(0xffffffffu, su0, d));
        su1 = add2(su1, __shfl_xor_sync(0xffffffffu, su1, d));
        su2 = add2(su2, __shfl_xor_sync(0xffffffffu, su2, d));
        su3 = add2(su3, __shfl_xor_sync(0xffffffffu, su3, d));
    }
    if (sub == 0) {
        float2 t;
        t = upk2(su0); atomicAdd(&g_scratch[b * 8 + 0], t.x); atomicAdd(&g_scratch[b * 8 + 1], t.y);
        t = upk2(su1); atomicAdd(&g_scratch[b * 8 + 2], t.x); atomicAdd(&g_scratch[b * 8 + 3], t.y);
        t = upk2(su2); atomicAdd(&g_scratch[b * 8 + 4], t.x); atomicAdd(&g_scratch[b * 8 + 5], t.y);
        t = upk2(su3); atomicAdd(&g_scratch[b * 8 + 6], t.x); atomicAdd(&g_scratch[b * 8 + 7], t.y);
    }

    __syncthreads();   // tiles + seg columns complete

    // ---- stage packed counts into the (now free) sW region ----
    #pragma unroll
    for (int c = 0; c < Cc; c++)
        sW[c * NTHR + tid] = (float)((cnt >> (6 * c)) & 63ull);
    __syncthreads();

    // ---- block reduction: 8 warps over 50 slots (40 seg + 10 counts) ----
    const int warp = tid >> 5;
    const int lane = tid & 31;
    for (int slot = warp; slot < 50; slot += 8) {
        if (slot < 40) {
            const unsigned* base = sSeg + slot * 256;
            float sx = 0.0f, sy = 0.0f;
            #pragma unroll
            for (int k = 0; k < 8; k++) {
                unsigned v = base[k * 32 + lane];
                float2 f = __bfloat1622float2(as_bf2(v));
                sx += f.x; sy += f.y;
            }
            #pragma unroll
            for (int d = 16; d > 0; d >>= 1) {
                sx += __shfl_xor_sync(0xffffffffu, sx, d);
                sy += __shfl_xor_sync(0xffffffffu, sy, d);
            }
            if (lane == 0) {
                int c = slot >> 2, dp = slot & 3;
                atomicAdd(&g_scratch[1024 + c * 8 + 2 * dp], sx);
                atomicAdd(&g_scratch[1024 + c * 8 + 2 * dp + 1], sy);
            }
        } else {
            const float* base = sW + (slot - 40) * NTHR;
            float s = 0.0f;
            #pragma unroll
            for (int k = 0; k < 8; k++) s += base[k * 32 + lane];
            #pragma unroll
            for (int d = 16; d > 0; d >>= 1)
                s += __shfl_xor_sync(0xffffffffu, s, d);
            if (lane == 0) atomicAdd(&g_scratch[1104 + (slot - 40)], s);
        }
    }

    // ---- last-block finalize ----
    __threadfence();
    __syncthreads();
    __shared__ int sLast;
    if (tid == 0) {
        unsigned prev = atomicAdd(&g_done, 1u);
        sLast = (prev == NBLK - 1u);
    }
    __syncthreads();
    if (!sLast) return;

    __threadfence();   // acquire: all blocks' scratch writes visible

    float* s_sum = sW;          // 1024 floats (sW region reused; sW spans 4160 f)
    float* dcn   = sW + 1024;   // 80 floats
    volatile float* gs = g_scratch;

    for (int i = tid; i < Bsz * Dd; i += NTHR) s_sum[i] = gs[i];
    if (tid < Cc * Dd) {
        int   c   = tid >> 3;
        float v   = dcg[tid];
        float upd = (gs[1024 + tid] - gs[1104 + c] * v)
                    * (1.0f / (float)(Bsz * Ntot));
        float nv  = v + upd;
        dcn[tid] = nv;
        out[Bsz * Cc + tid] = nv;          // digit_caps_new tail
    }
    __syncthreads();

    // self-clean scratch + counter for the next graph replay
    for (int i = tid; i < 1120; i += NTHR) g_scratch[i] = 0.0f;
    if (tid == 0) g_done = 0u;

    for (int idx = tid; idx < Bsz * Cc; idx += NTHR) {
        int bb = idx / Cc;
        int c  = idx - bb * Cc;
        float s = 0.0f;
        #pragma unroll
        for (int d = 0; d < Dd; d++) s += s_sum[bb * 8 + d] * dcn[c * 8 + d];
        out[idx] = s * (1.0f / (float)Ntot);
    }
}

extern "C" void kernel_launch(void* const* d_in, const int* in_sizes, int n_in,
                              void* d_out, int out_size)
{
    const float* xin = (const float*)d_in[0];  // inputs [128,12,12,32,8]
    const float* Wg  = (const float*)d_in[1];  // W [4608,8,32]
    const float* dcg = (const float*)d_in[2];  // digit_caps [10,8]
    float* out = (float*)d_out;

    size_t smemBytes = (size_t)(JB * WSTR + BB * XSTR + NSEG * 256) * sizeof(float);
    cudaFuncSetAttribute(caps_main_kernel,
                         cudaFuncAttributeMaxDynamicSharedMemorySize,
                         (int)smemBytes);
    dim3 grid(Jtot / JB, Bsz / BB);
    caps_main_kernel<<<grid, NTHR, smemBytes>>>(xin, Wg, dcg, out);
}

// round 15
// speedup vs baseline: 1.4466x; 1.4466x over previous
#include <cuda_runtime.h>
#include <cuda_bf16.h>

// DigitCaps for GB300 (sm_103a), round 15: EXACT round-3 main loop (51.7us
// proven) + single delta: finalize fused into the last block (removes the
// measured 6.7us tail kernel). No other changes.
//
//   output[b,c] = (sum_n u[b,n,:]) . dc_new[c,:] / N
//   dc_new      = dc + (seg_u - counts*dc) / (B*N)

#define Bsz    128
#define Jtot   4608
#define Cc     10
#define Dd     8
#define Mm     4
#define Ntot   (Jtot * Mm)          // 18432

#define JB     32
#define BB     32
#define NTHR   256
#define WSTR   260                  // padded W row stride (floats)
#define XSTR   258                  // padded X row stride (floats)
#define NPAIR  45                   // 40 seg bf16x2 pairs + 5 count pairs
#define NBLK   ((Jtot / JB) * (Bsz / BB))   // 576

// scratch: [0,1024) sum_u[b][d]; [1024,1104) seg[c*8+d]; [1104,1114) cnt[c]
__device__ float    g_scratch[1120];
__device__ unsigned g_done;

// ---- packed f32x2 helpers (ptxas never emits FFMA2 from C++) ----
__device__ __forceinline__ unsigned long long pk2(float lo, float hi) {
    unsigned long long r;
    asm("mov.b64 %0, {%1, %2};" : "=l"(r) : "f"(lo), "f"(hi));
    return r;
}
__device__ __forceinline__ float2 upk2(unsigned long long a) {
    float2 r;
    asm("mov.b64 {%0, %1}, %2;" : "=f"(r.x), "=f"(r.y) : "l"(a));
    return r;
}
__device__ __forceinline__ unsigned long long fma2(unsigned long long a,
                                                   unsigned long long b,
                                                   unsigned long long c) {
    unsigned long long d;
    asm("fma.rn.f32x2 %0, %1, %2, %3;" : "=l"(d) : "l"(a), "l"(b), "l"(c));
    return d;
}
__device__ __forceinline__ unsigned long long mul2(unsigned long long a,
                                                   unsigned long long b) {
    unsigned long long d;
    asm("mul.rn.f32x2 %0, %1, %2;" : "=l"(d) : "l"(a), "l"(b));
    return d;
}
__device__ __forceinline__ unsigned long long add2(unsigned long long a,
                                                   unsigned long long b) {
    unsigned long long d;
    asm("add.rn.f32x2 %0, %1, %2;" : "=l"(d) : "l"(a), "l"(b));
    return d;
}
// pack-to-bf16x2: lo float -> bits[15:0], hi float -> bits[31:16]
__device__ __forceinline__ unsigned cvt_bf16x2(unsigned long long p) {
    float2 t = upk2(p);
    unsigned r;
    asm("cvt.rn.bf16x2.f32 %0, %1, %2;" : "=r"(r) : "f"(t.y), "f"(t.x));
    return r;
}
__device__ __forceinline__ __nv_bfloat162 as_bf2(unsigned v) {
    return *(__nv_bfloat162*)&v;
}

extern __shared__ float smem[];

__global__ __launch_bounds__(NTHR, 2)
void caps_main_kernel(const float* __restrict__ xin,   // [B, J, 8]
                      const float* __restrict__ Wg,    // [J, 8, 32]
                      const float* __restrict__ dcg,   // [10, 8]
                      float* __restrict__ out)         // [128*10 + 80]
{
    float*    sW   = smem;                               // JB*WSTR = 8320 f
    float*    sX   = sW + JB * WSTR;                     // BB*XSTR = 8256 f
    unsigned* sSeg = (unsigned*)(sX + BB * XSTR);        // NPAIR*256 u32

    const int tid = threadIdx.x;
    const int j0  = blockIdx.x * JB;
    const int b0  = blockIdx.y * BB;

    // ---- stage W tile (padded rows, float4) ----
    {
        const float4* src = (const float4*)(Wg + (size_t)j0 * 256);
        #pragma unroll 4
        for (int i = tid; i < JB * 64; i += NTHR) {
            int jl = i >> 6, r = i & 63;
            ((float4*)sW)[jl * (WSTR / 4) + r] = src[i];
        }
    }
    // ---- stage X tile (padded rows, float2) ----
    {
        for (int i = tid; i < BB * 128; i += NTHR) {
            int bl = i >> 7, r = i & 127;
            const float2* src =
                (const float2*)(xin + (size_t)(b0 + bl) * (Jtot * 8) + (size_t)j0 * 8);
            ((float2*)sX)[bl * (XSTR / 2) + r] = src[r];
        }
    }
    // ---- zero private seg columns ----
    for (int i = tid; i < NPAIR * 256; i += NTHR) sSeg[i] = 0u;

    // ---- digit_caps as 40 f32x2 pairs in registers ----
    unsigned long long rdc[Cc * 4];
    #pragma unroll
    for (int i = 0; i < Cc * 4; i++) {
        float2 v = ((const float2*)dcg)[i];
        rdc[i] = pk2(v.x, v.y);
    }

    __syncthreads();

    const int bl  = tid >> 3;
    const int sub = tid & 7;
    const int b   = b0 + bl;

    unsigned long long su0 = 0, su1 = 0, su2 = 0, su3 = 0;
    const float2* xrow = (const float2*)sX + bl * (XSTR / 2);

    for (int it = 0; it < 16; ++it) {
        const int p  = it * 8 + sub;
        const int jl = p >> 2;
        const int m  = p & 3;

        const float2* xs = xrow + jl * 4;
        const float4* w4 = (const float4*)sW + jl * (WSTR / 4) + m * 2;

        unsigned long long u0 = 0, u1 = 0, u2 = 0, u3 = 0;
        #pragma unroll
        for (int k = 0; k < 4; k++) {
            float2 xp = xs[k];
            unsigned long long xa = pk2(xp.x, xp.x);
            unsigned long long xb = pk2(xp.y, xp.y);
            float4 wA = w4[(2 * k) * 8];
            float4 wB = w4[(2 * k) * 8 + 1];
            u0 = fma2(xa, pk2(wA.x, wA.y), u0);
            u1 = fma2(xa, pk2(wA.z, wA.w), u1);
            u2 = fma2(xa, pk2(wB.x, wB.y), u2);
            u3 = fma2(xa, pk2(wB.z, wB.w), u3);
            float4 wC = w4[(2 * k + 1) * 8];
            float4 wD = w4[(2 * k + 1) * 8 + 1];
            u0 = fma2(xb, pk2(wC.x, wC.y), u0);
            u1 = fma2(xb, pk2(wC.z, wC.w), u1);
            u2 = fma2(xb, pk2(wD.x, wD.y), u2);
            u3 = fma2(xb, pk2(wD.z, wD.w), u3);
        }

        su0 = add2(su0, u0); su1 = add2(su1, u1);
        su2 = add2(su2, u2); su3 = add2(su3, u3);

        // argmax over classes (first-max semantics) — r3 predicate form
        float best;
        int   wbest = 0;
        {
            unsigned long long acc = mul2(u0, rdc[0]);
            acc = fma2(u1, rdc[1], acc);
            acc = fma2(u2, rdc[2], acc);
            acc = fma2(u3, rdc[3], acc);
            float2 t = upk2(acc);
            best = t.x + t.y;
        }
        #pragma unroll
        for (int c = 1; c < Cc; c++) {
            unsigned long long acc = mul2(u0, rdc[4 * c]);
            acc = fma2(u1, rdc[4 * c + 1], acc);
            acc = fma2(u2, rdc[4 * c + 2], acc);
            acc = fma2(u3, rdc[4 * c + 3], acc);
            float2 t = upk2(acc);
            float  s = t.x + t.y;
            if (s > best) { best = s; wbest = c; }
        }

        // per-thread-private bf16x2 segment accumulation (bank = tid%32)
        unsigned v0 = cvt_bf16x2(u0), v1 = cvt_bf16x2(u1);
        unsigned v2 = cvt_bf16x2(u2), v3 = cvt_bf16x2(u3);
        unsigned* segp = sSeg + wbest * 4 * 256 + tid;
        {
            unsigned o;
            __nv_bfloat162 r;
            o = segp[0];
            r = __hadd2(as_bf2(o), as_bf2(v0));
            segp[0] = *(unsigned*)&r;
            o = segp[256];
            r = __hadd2(as_bf2(o), as_bf2(v1));
            segp[256] = *(unsigned*)&r;
            o = segp[512];
            r = __hadd2(as_bf2(o), as_bf2(v2));
            segp[512] = *(unsigned*)&r;
            o = segp[768];
            r = __hadd2(as_bf2(o), as_bf2(v3));
            segp[768] = *(unsigned*)&r;
            // count: bf16 1.0 into the (wbest&1) half
            unsigned inc = (wbest & 1) ? 0x3F800000u : 0x00003F80u;
            unsigned* cp = sSeg + (40 + (wbest >> 1)) * 256 + tid;
            o = *cp;
            r = __hadd2(as_bf2(o), as_bf2(inc));
            *cp = *(unsigned*)&r;
        }
    }

    // ---- sum_u: reduce over the 8 threads sharing b ----
    #pragma unroll
    for (int d = 1; d < 8; d <<= 1) {
        su0 = add2(su0, __shfl_xor_sync(0xffffffffu, su0, d));
        su1 = add2(su1, __shfl_xor_sync(0xffffffffu, su1, d));
        su2 = add2(su2, __shfl_xor_sync(0xffffffffu, su2, d));
        su3 = add2(su3, __shfl_xor_sync(0xffffffffu, su3, d));
    }
    if (sub == 0) {
        float2 t;
        t = upk2(su0); atomicAdd(&g_scratch[b * 8 + 0], t.x); atomicAdd(&g_scratch[b * 8 + 1], t.y);
        t = upk2(su1); atomicAdd(&g_scratch[b * 8 + 2], t.x); atomicAdd(&g_scratch[b * 8 + 3], t.y);
        t = upk2(su2); atomicAdd(&g_scratch[b * 8 + 4], t.x); atomicAdd(&g_scratch[b * 8 + 5], t.y);
        t = upk2(su3); atomicAdd(&g_scratch[b * 8 + 6], t.x); atomicAdd(&g_scratch[b * 8 + 7], t.y);
    }

    __syncthreads();

    // ---- reduce the 45 private-pair slots; warp per slot, conflict-free ----
    const int warp = tid >> 5;
    const int lane = tid & 31;
    for (int slot = warp; slot < NPAIR; slot += 8) {
        const unsigned* base = sSeg + slot * 256;
        float sx = 0.0f, sy = 0.0f;
        #pragma unroll
        for (int k = 0; k < 8; k++) {
            unsigned v = base[k * 32 + lane];
            float2 f = __bfloat1622float2(as_bf2(v));
            sx += f.x; sy += f.y;
        }
        #pragma unroll
        for (int d = 16; d > 0; d >>= 1) {
            sx += __shfl_xor_sync(0xffffffffu, sx, d);
            sy += __shfl_xor_sync(0xffffffffu, sy, d);
        }
        if (lane == 0) {
            int g0;
            if (slot < 40) {
                int c = slot >> 2, dp = slot & 3;
                g0 = 1024 + c * 8 + 2 * dp;
            } else {
                g0 = 1104 + 2 * (slot - 40);
            }
            atomicAdd(&g_scratch[g0], sx);
            atomicAdd(&g_scratch[g0 + 1], sy);
        }
    }

    // ---- last-block finalize (the single delta vs round-3) ----
    __threadfence();
    __syncthreads();
    __shared__ int sLast;
    if (tid == 0) {
        unsigned prev = atomicAdd(&g_done, 1u);
        sLast = (prev == NBLK - 1u);
    }
    __syncthreads();
    if (!sLast) return;

    __threadfence();   // acquire: all blocks' scratch writes visible

    float* s_sum = sW;          // 1024 floats (sW region reused)
    float* dcn   = sW + 1024;   // 80 floats
    volatile float* gs = g_scratch;

    for (int i = tid; i < Bsz * Dd; i += NTHR) s_sum[i] = gs[i];
    if (tid < Cc * Dd) {
        int   c   = tid >> 3;
        float v   = dcg[tid];
        float upd = (gs[1024 + tid] - gs[1104 + c] * v)
                    * (1.0f / (float)(Bsz * Ntot));
        float nv  = v + upd;
        dcn[tid] = nv;
        out[Bsz * Cc + tid] = nv;          // digit_caps_new tail
    }
    __syncthreads();

    // self-clean scratch + counter for the next graph replay
    for (int i = tid; i < 1120; i += NTHR) g_scratch[i] = 0.0f;
    if (tid == 0) g_done = 0u;

    for (int idx = tid; idx < Bsz * Cc; idx += NTHR) {
        int bb = idx / Cc;
        int c  = idx - bb * Cc;
        float s = 0.0f;
        #pragma unroll
        for (int d = 0; d < Dd; d++) s += s_sum[bb * 8 + d] * dcn[c * 8 + d];
        out[idx] = s * (1.0f / (float)Ntot);
    }
}

extern "C" void kernel_launch(void* const* d_in, const int* in_sizes, int n_in,
                              void* d_out, int out_size)
{
    const float* xin = (const float*)d_in[0];  // inputs [128,12,12,32,8]
    const float* Wg  = (const float*)d_in[1];  // W [4608,8,32]
    const float* dcg = (const float*)d_in[2];  // digit_caps [10,8]
    float* out = (float*)d_out;

    size_t smemBytes = (size_t)(JB * WSTR + BB * XSTR + NPAIR * 256) * sizeof(float);
    cudaFuncSetAttribute(caps_main_kernel,
                         cudaFuncAttributeMaxDynamicSharedMemorySize,
                         (int)smemBytes);
    dim3 grid(Jtot / JB, Bsz / BB);
    caps_main_kernel<<<grid, NTHR, smemBytes>>>(xin, Wg, dcg, out);
}

// round 16
// speedup vs baseline: 1.5637x; 1.0810x over previous
#include <cuda_runtime.h>
#include <cuda_bf16.h>

// DigitCaps for GB300 (sm_103a), round 16.
// EXACT round-3 structure (two kernels, 51.7us proven) + single main-loop
// delta: segment RMW vectorized to 2x 64-bit LDS/STS (was 5x 32-bit) and
// counts moved to a packed register. Nothing else changed.
//
//   output[b,c] = (sum_n u[b,n,:]) . dc_new[c,:] / N
//   dc_new      = dc + (seg_u - counts*dc) / (B*N)

#define Bsz    128
#define Jtot   4608
#define Cc     10
#define Dd     8
#define Mm     4
#define Ntot   (Jtot * Mm)          // 18432

#define JB     32
#define BB     32
#define NTHR   256
#define WSTR   260                  // padded W row stride (floats)
#define XSTR   258                  // padded X row stride (floats)
#define NSEG64 20                   // 10 classes x 2 uint2 slots (8 bf16 dims)

// scratch: [0,1024) sum_u[b][d]; [1024,1104) seg[c*8+d]; [1104,1114) cnt[c]
// zero at module load; caps_final re-zeroes after consuming.
__device__ float g_scratch[1120];

// ---- packed f32x2 helpers (ptxas never emits FFMA2 from C++) ----
__device__ __forceinline__ unsigned long long pk2(float lo, float hi) {
    unsigned long long r;
    asm("mov.b64 %0, {%1, %2};" : "=l"(r) : "f"(lo), "f"(hi));
    return r;
}
__device__ __forceinline__ float2 upk2(unsigned long long a) {
    float2 r;
    asm("mov.b64 {%0, %1}, %2;" : "=f"(r.x), "=f"(r.y) : "l"(a));
    return r;
}
__device__ __forceinline__ unsigned long long fma2(unsigned long long a,
                                                   unsigned long long b,
                                                   unsigned long long c) {
    unsigned long long d;
    asm("fma.rn.f32x2 %0, %1, %2, %3;" : "=l"(d) : "l"(a), "l"(b), "l"(c));
    return d;
}
__device__ __forceinline__ unsigned long long mul2(unsigned long long a,
                                                   unsigned long long b) {
    unsigned long long d;
    asm("mul.rn.f32x2 %0, %1, %2;" : "=l"(d) : "l"(a), "l"(b));
    return d;
}
__device__ __forceinline__ unsigned long long add2(unsigned long long a,
                                                   unsigned long long b) {
    unsigned long long d;
    asm("add.rn.f32x2 %0, %1, %2;" : "=l"(d) : "l"(a), "l"(b));
    return d;
}
// pack-to-bf16x2: lo float -> bits[15:0], hi float -> bits[31:16]
__device__ __forceinline__ unsigned cvt_bf16x2(unsigned long long p) {
    float2 t = upk2(p);
    unsigned r;
    asm("cvt.rn.bf16x2.f32 %0, %1, %2;" : "=r"(r) : "f"(t.y), "f"(t.x));
    return r;
}
__device__ __forceinline__ __nv_bfloat162 as_bf2(unsigned v) {
    return *(__nv_bfloat162*)&v;
}
__device__ __forceinline__ unsigned hadd2u(unsigned a, unsigned b) {
    __nv_bfloat162 r = __hadd2(as_bf2(a), as_bf2(b));
    return *(unsigned*)&r;
}

extern __shared__ float smem[];

__global__ __launch_bounds__(NTHR, 2)
void caps_main_kernel(const float* __restrict__ xin,   // [B, J, 8]
                      const float* __restrict__ Wg,    // [J, 8, 32]
                      const float* __restrict__ dcg)   // [10, 8]
{
    float* sW   = smem;                          // JB*WSTR = 8320 f
    float* sX   = sW + JB * WSTR;                // BB*XSTR = 8256 f
    uint2* sSeg = (uint2*)(sX + BB * XSTR);      // NSEG64*256 uint2 (8B each)

    const int tid = threadIdx.x;
    const int j0  = blockIdx.x * JB;
    const int b0  = blockIdx.y * BB;

    // ---- stage W tile (padded rows, float4) ----
    {
        const float4* src = (const float4*)(Wg + (size_t)j0 * 256);
        #pragma unroll 4
        for (int i = tid; i < JB * 64; i += NTHR) {
            int jl = i >> 6, r = i & 63;
            ((float4*)sW)[jl * (WSTR / 4) + r] = src[i];
        }
    }
    // ---- stage X tile (padded rows, float2) ----
    {
        for (int i = tid; i < BB * 128; i += NTHR) {
            int bl = i >> 7, r = i & 127;
            const float2* src =
                (const float2*)(xin + (size_t)(b0 + bl) * (Jtot * 8) + (size_t)j0 * 8);
            ((float2*)sX)[bl * (XSTR / 2) + r] = src[r];
        }
    }
    // ---- zero private seg columns ----
    {
        uint2 z = make_uint2(0u, 0u);
        for (int i = tid; i < NSEG64 * 256; i += NTHR) sSeg[i] = z;
    }

    // ---- digit_caps as 40 f32x2 pairs in registers ----
    unsigned long long rdc[Cc * 4];
    #pragma unroll
    for (int i = 0; i < Cc * 4; i++) {
        float2 v = ((const float2*)dcg)[i];
        rdc[i] = pk2(v.x, v.y);
    }

    __syncthreads();

    const int bl  = tid >> 3;
    const int sub = tid & 7;
    const int b   = b0 + bl;

    unsigned long long su0 = 0, su1 = 0, su2 = 0, su3 = 0;
    unsigned long long cnt = 0;     // 10 x 6-bit packed counts (max 16/thread)
    const float2* xrow = (const float2*)sX + bl * (XSTR / 2);

    for (int it = 0; it < 16; ++it) {
        const int p  = it * 8 + sub;
        const int jl = p >> 2;
        const int m  = p & 3;

        const float2* xs = xrow + jl * 4;
        const float4* w4 = (const float4*)sW + jl * (WSTR / 4) + m * 2;

        unsigned long long u0 = 0, u1 = 0, u2 = 0, u3 = 0;
        #pragma unroll
        for (int k = 0; k < 4; k++) {
            float2 xp = xs[k];
            unsigned long long xa = pk2(xp.x, xp.x);
            unsigned long long xb = pk2(xp.y, xp.y);
            float4 wA = w4[(2 * k) * 8];
            float4 wB = w4[(2 * k) * 8 + 1];
            u0 = fma2(xa, pk2(wA.x, wA.y), u0);
            u1 = fma2(xa, pk2(wA.z, wA.w), u1);
            u2 = fma2(xa, pk2(wB.x, wB.y), u2);
            u3 = fma2(xa, pk2(wB.z, wB.w), u3);
            float4 wC = w4[(2 * k + 1) * 8];
            float4 wD = w4[(2 * k + 1) * 8 + 1];
            u0 = fma2(xb, pk2(wC.x, wC.y), u0);
            u1 = fma2(xb, pk2(wC.z, wC.w), u1);
            u2 = fma2(xb, pk2(wD.x, wD.y), u2);
            u3 = fma2(xb, pk2(wD.z, wD.w), u3);
        }

        su0 = add2(su0, u0); su1 = add2(su1, u1);
        su2 = add2(su2, u2); su3 = add2(su3, u3);

        // argmax over classes (first-max semantics) — r3 predicate form
        float best;
        int   wbest = 0;
        {
            unsigned long long acc = mul2(u0, rdc[0]);
            acc = fma2(u1, rdc[1], acc);
            acc = fma2(u2, rdc[2], acc);
            acc = fma2(u3, rdc[3], acc);
            float2 t = upk2(acc);
            best = t.x + t.y;
        }
        #pragma unroll
        for (int c = 1; c < Cc; c++) {
            unsigned long long acc = mul2(u0, rdc[4 * c]);
            acc = fma2(u1, rdc[4 * c + 1], acc);
            acc = fma2(u2, rdc[4 * c + 2], acc);
            acc = fma2(u3, rdc[4 * c + 3], acc);
            float2 t = upk2(acc);
            float  s = t.x + t.y;
            if (s > best) { best = s; wbest = c; }
        }

        // bf16 votes
        unsigned v0 = cvt_bf16x2(u0), v1 = cvt_bf16x2(u1);
        unsigned v2 = cvt_bf16x2(u2), v3 = cvt_bf16x2(u3);

        // per-thread-private seg accumulation: TWO 64-bit RMWs (was five 32-bit)
        uint2* segp = sSeg + wbest * 2 * 256 + tid;
        {
            uint2 o0 = segp[0];
            uint2 o1 = segp[256];
            o0.x = hadd2u(o0.x, v0); o0.y = hadd2u(o0.y, v1);
            o1.x = hadd2u(o1.x, v2); o1.y = hadd2u(o1.y, v3);
            segp[0]   = o0;
            segp[256] = o1;
        }
        cnt += 1ull << (6 * wbest);
    }

    // ---- sum_u: reduce over the 8 threads sharing b ----
    #pragma unroll
    for (int d = 1; d < 8; d <<= 1) {
        su0 = add2(su0, __shfl_xor_sync(0xffffffffu, su0, d));
        su1 = add2(su1, __shfl_xor_sync(0xffffffffu, su1, d));
        su2 = add2(su2, __shfl_xor_sync(0xffffffffu, su2, d));
        su3 = add2(su3, __shfl_xor_sync(0xffffffffu, su3, d));
    }
    if (sub == 0) {
        float2 t;
        t = upk2(su0); atomicAdd(&g_scratch[b * 8 + 0], t.x); atomicAdd(&g_scratch[b * 8 + 1], t.y);
        t = upk2(su1); atomicAdd(&g_scratch[b * 8 + 2], t.x); atomicAdd(&g_scratch[b * 8 + 3], t.y);
        t = upk2(su2); atomicAdd(&g_scratch[b * 8 + 4], t.x); atomicAdd(&g_scratch[b * 8 + 5], t.y);
        t = upk2(su3); atomicAdd(&g_scratch[b * 8 + 6], t.x); atomicAdd(&g_scratch[b * 8 + 7], t.y);
    }

    __syncthreads();   // tiles + seg columns complete

    // ---- stage packed counts into the (now free) sW region ----
    #pragma unroll
    for (int c = 0; c < Cc; c++)
        sW[c * NTHR + tid] = (float)((cnt >> (6 * c)) & 63ull);
    __syncthreads();

    // ---- block reduction: 8 warps over 30 slots (20 seg64 + 10 counts) ----
    const int warp = tid >> 5;
    const int lane = tid & 31;
    for (int slot = warp; slot < NSEG64 + Cc; slot += 8) {
        if (slot < NSEG64) {
            const uint2* base = sSeg + slot * 256;
            float s0 = 0.0f, s1 = 0.0f, s2 = 0.0f, s3 = 0.0f;
            #pragma unroll
            for (int k = 0; k < 8; k++) {
                uint2 v = base[k * 32 + lane];
                float2 fa = __bfloat1622float2(as_bf2(v.x));
                float2 fb = __bfloat1622float2(as_bf2(v.y));
                s0 += fa.x; s1 += fa.y; s2 += fb.x; s3 += fb.y;
            }
            #pragma unroll
            for (int d = 16; d > 0; d >>= 1) {
                s0 += __shfl_xor_sync(0xffffffffu, s0, d);
                s1 += __shfl_xor_sync(0xffffffffu, s1, d);
                s2 += __shfl_xor_sync(0xffffffffu, s2, d);
                s3 += __shfl_xor_sync(0xffffffffu, s3, d);
            }
            if (lane == 0) {
                int c = slot >> 1, half = slot & 1;   // half: dims 0-3 / 4-7
                int g0 = 1024 + c * 8 + half * 4;
                atomicAdd(&g_scratch[g0 + 0], s0);
                atomicAdd(&g_scratch[g0 + 1], s1);
                atomicAdd(&g_scratch[g0 + 2], s2);
                atomicAdd(&g_scratch[g0 + 3], s3);
            }
        } else {
            const float* base = sW + (slot - NSEG64) * NTHR;
            float s = 0.0f;
            #pragma unroll
            for (int k = 0; k < 8; k++) s += base[k * 32 + lane];
            #pragma unroll
            for (int d = 16; d > 0; d >>= 1)
                s += __shfl_xor_sync(0xffffffffu, s, d);
            if (lane == 0) atomicAdd(&g_scratch[1104 + (slot - NSEG64)], s);
        }
    }
}

__global__ void caps_final_kernel(const float* __restrict__ dcg,
                                  float* __restrict__ out)
{
    __shared__ float s_sum[Bsz * Dd];
    __shared__ float dcn[Cc * Dd];
    const int tid = threadIdx.x;   // 256 threads, 1 block

    for (int i = tid; i < Bsz * Dd; i += 256) s_sum[i] = g_scratch[i];

    if (tid < Cc * Dd) {
        int   c   = tid >> 3;
        float v   = dcg[tid];
        float upd = (g_scratch[1024 + tid] - g_scratch[1104 + c] * v)
                    * (1.0f / (float)(Bsz * Ntot));
        float nv  = v + upd;
        dcn[tid] = nv;
        out[Bsz * Cc + tid] = nv;          // digit_caps_new tail
    }
    __syncthreads();

    // self-clean scratch for the next graph replay
    for (int i = tid; i < 1120; i += 256) g_scratch[i] = 0.0f;

    for (int idx = tid; idx < Bsz * Cc; idx += 256) {
        int b = idx / Cc;
        int c = idx - b * Cc;
        float s = 0.0f;
        #pragma unroll
        for (int d = 0; d < Dd; d++) s += s_sum[b * 8 + d] * dcn[c * 8 + d];
        out[idx] = s * (1.0f / (float)Ntot);
    }
}

extern "C" void kernel_launch(void* const* d_in, const int* in_sizes, int n_in,
                              void* d_out, int out_size)
{
    const float* xin = (const float*)d_in[0];  // inputs [128,12,12,32,8]
    const float* Wg  = (const float*)d_in[1];  // W [4608,8,32]
    const float* dcg = (const float*)d_in[2];  // digit_caps [10,8]
    float* out = (float*)d_out;

    size_t smemBytes = (size_t)(JB * WSTR + BB * XSTR) * sizeof(float)
                     + (size_t)NSEG64 * 256 * sizeof(uint2);
    cudaFuncSetAttribute(caps_main_kernel,
                         cudaFuncAttributeMaxDynamicSharedMemorySize,
                         (int)smemBytes);
    dim3 grid(Jtot / JB, Bsz / BB);
    caps_main_kernel<<<grid, NTHR, smemBytes>>>(xin, Wg, dcg);

    caps_final_kernel<<<1, 256>>>(dcg, out);
}